// round 7
// baseline (speedup 1.0000x reference)
#include <cuda_runtime.h>
#include <cstdint>

#define N_NODES 50000
#define N_REL 8
#define N_EDGE 64000
#define D 128

// ---------------- common helpers ----------------
__device__ __forceinline__ uint32_t f2tf32(float f) {
    uint32_t r;
    asm("cvt.rna.tf32.f32 %0, %1;" : "=r"(r) : "f"(f));
    return r;
}
__device__ __forceinline__ void cp16(uint32_t sa, const float* g) {
    asm volatile("cp.async.cg.shared.global [%0], [%1], 16;" ::"r"(sa), "l"(g));
}
__device__ __forceinline__ void cp_commit() { asm volatile("cp.async.commit_group;"); }
template <int N>
__device__ __forceinline__ void cp_wait() { asm volatile("cp.async.wait_group %0;" ::"n"(N)); }

__device__ __forceinline__ void mma_tf32(float c[4], const uint32_t a[4], const uint32_t b[2]) {
    asm volatile(
        "mma.sync.aligned.m16n8k8.row.col.f32.tf32.tf32.f32 "
        "{%0,%1,%2,%3}, {%4,%5,%6,%7}, {%8,%9}, {%0,%1,%2,%3};\n"
        : "+f"(c[0]), "+f"(c[1]), "+f"(c[2]), "+f"(c[3])
        : "r"(a[0]), "r"(a[1]), "r"(a[2]), "r"(a[3]), "r"(b[0]), "r"(b[1]));
}

// Pre-rounded (RNA tf32) weights: relations + root. Plain [k][n] layouts.
__device__ float g_wt[N_REL * D * D];
__device__ float g_rw[D * D];

extern "C" __global__ void pack_w_kernel(const float* __restrict__ weight,
                                         const float* __restrict__ root_w) {
    int r = blockIdx.x;
    if (r < N_REL) {
        for (int i = threadIdx.x; i < D * D; i += blockDim.x)
            g_wt[r * D * D + i] = __uint_as_float(f2tf32(weight[r * D * D + i]));
    } else {
        for (int i = threadIdx.x; i < D * D; i += blockDim.x)
            g_rw[i] = __uint_as_float(f2tf32(root_w[i]));
    }
}

// ---------------------------------------------------------------------------
// Edge kernel v2: B resident in smem for 4 tiles per CTA.
// smem: Bres[128][136] (69632 B) | A0[128][36] | A1[128][36] (36864 B) = 104 KB
// C staging overlays the A buffers in two 64-row halves (stride 132).
// ---------------------------------------------------------------------------
#define BRES_STRIDE 136
#define BRES_FLOATS (128 * BRES_STRIDE)   // 17408
#define EA_STRIDE 36
#define EA_CHUNK (128 * EA_STRIDE)        // 4608
#define TILES_PER_CTA 4
#define EDGE_SMEM ((BRES_FLOATS + 2 * EA_CHUNK) * 4)  // 106496 B

extern "C" __global__ void __launch_bounds__(256, 2)
edge_kernel(const float* __restrict__ x, const int* __restrict__ src,
            const int* __restrict__ dst, const float* __restrict__ ew,
            float* __restrict__ out) {
    extern __shared__ float smem[];
    float* Bs = smem;
    float* Asb[2] = {smem + BRES_FLOATS, smem + BRES_FLOATS + EA_CHUNK};
    float* Cs = smem + BRES_FLOATS;  // overlays A buffers: 64 rows x 132 = 8448 <= 9216

    const int tid = threadIdx.x;
    const int lane = tid & 31, warp = tid >> 5;
    const int g = lane >> 2, tg = lane & 3;
    const int mw = warp >> 1, nw = warp & 1;
    const int r = blockIdx.y;
    const int tile0 = blockIdx.x * TILES_PER_CTA;
    const float* W = g_wt + (size_t)r * D * D;

    const uint32_t bs_base = (uint32_t)__cvta_generic_to_shared(Bs);
    const uint32_t a_base[2] = {(uint32_t)__cvta_generic_to_shared(Asb[0]),
                                (uint32_t)__cvta_generic_to_shared(Asb[1])};

    // gather A chunk c of tile with edge base eb into buffer buf
    auto issueA = [&](int eb, int c, int buf) {
#pragma unroll
        for (int it = 0; it < 4; it++) {
            int s = tid + it * 256;
            int row = s >> 3, off = (s & 7) * 4;
            int srow = __ldg(&src[eb + row]);
            cp16(a_base[buf] + (uint32_t)(row * EA_STRIDE + off) * 4,
                 x + (size_t)srow * D + c * 32 + off);
        }
    };

    // prologue group: resident B + A(tile0, chunk0)
    {
#pragma unroll
        for (int it = 0; it < 16; it++) {
            int j = tid + it * 256;
            int k = j >> 5, q = j & 31;
            cp16(bs_base + (uint32_t)(k * BRES_STRIDE + q * 4) * 4,
                 W + (size_t)k * D + q * 4);
        }
        issueA(r * N_EDGE + tile0 * 128, 0, 0);
        cp_commit();
    }

    for (int t = 0; t < TILES_PER_CTA; t++) {
        const int eb = r * N_EDGE + (tile0 + t) * 128;

        float acc[2][8][4];
#pragma unroll
        for (int mi = 0; mi < 2; mi++)
#pragma unroll
            for (int j = 0; j < 8; j++)
#pragma unroll
                for (int c4 = 0; c4 < 4; c4++) acc[mi][j][c4] = 0.f;

#pragma unroll
        for (int c = 0; c < 4; c++) {
            if (c + 1 < 4) { issueA(eb, c + 1, (c + 1) & 1); cp_commit(); cp_wait<1>(); }
            else cp_wait<0>();
            __syncthreads();

            // compute chunk c: A from Asb[c&1], B rows c*32.. from resident Bs
            const float* As = Asb[c & 1];
            const float* Bc = Bs + c * 32 * BRES_STRIDE;
#pragma unroll
            for (int k0 = 0; k0 < 32; k0 += 8) {
                uint32_t a[2][4];
#pragma unroll
                for (int mi = 0; mi < 2; mi++) {
                    const float* Ab = As + (mw * 32 + mi * 16 + g) * EA_STRIDE + k0;
                    a[mi][0] = __float_as_uint(Ab[tg]);
                    a[mi][1] = __float_as_uint(Ab[8 * EA_STRIDE + tg]);
                    a[mi][2] = __float_as_uint(Ab[tg + 4]);
                    a[mi][3] = __float_as_uint(Ab[8 * EA_STRIDE + tg + 4]);
                }
                uint32_t b[8][2];
#pragma unroll
                for (int j = 0; j < 8; j++) {
                    int col = nw * 64 + 8 * j + g;
                    b[j][0] = __float_as_uint(Bc[(k0 + tg) * BRES_STRIDE + col]);
                    b[j][1] = __float_as_uint(Bc[(k0 + tg + 4) * BRES_STRIDE + col]);
                }
#pragma unroll
                for (int mi = 0; mi < 2; mi++)
#pragma unroll
                    for (int j = 0; j < 8; j++)
                        mma_tf32(acc[mi][j], a[mi], b[j]);
            }
            __syncthreads();
        }

        // scatter in two 64-row halves staged through the A-buffer region
#pragma unroll
        for (int h = 0; h < 2; h++) {
            if ((mw >> 1) == h) {
                const int mwl = mw & 1;
#pragma unroll
                for (int mi = 0; mi < 2; mi++) {
                    int lrow = mwl * 32 + mi * 16 + g;  // 0..63 local
                    float w0 = __ldg(&ew[eb + 64 * h + lrow]);
                    float w1 = __ldg(&ew[eb + 64 * h + lrow + 8]);
#pragma unroll
                    for (int j = 0; j < 8; j++) {
                        int col = nw * 64 + 8 * j + 2 * tg;
                        *(float2*)&Cs[lrow * 132 + col] =
                            make_float2(acc[mi][j][0] * w0, acc[mi][j][1] * w0);
                        *(float2*)&Cs[(lrow + 8) * 132 + col] =
                            make_float2(acc[mi][j][2] * w1, acc[mi][j][3] * w1);
                    }
                }
            }
            __syncthreads();
#pragma unroll
            for (int it = 0; it < 8; it++) {
                int s = tid + it * 256;
                int lrow = s >> 5, q = s & 31;
                int d = __ldg(&dst[eb + 64 * h + lrow]);
                const float4 v = *(const float4*)&Cs[lrow * 132 + q * 4];
                float* p = out + (size_t)d * D + q * 4;
                asm volatile("red.global.add.v4.f32 [%0], {%1,%2,%3,%4};"
                             ::"l"(p), "f"(v.x), "f"(v.y), "f"(v.z), "f"(v.w)
                             : "memory");
            }
            __syncthreads();
        }

        // A buffers free again: prefetch next tile's chunk 0
        if (t + 1 < TILES_PER_CTA) {
            issueA(r * N_EDGE + (tile0 + t + 1) * 128, 0, 0);
            cp_commit();
        }
    }
}

// ---------------------------------------------------------------------------
// Root kernel (unchanged, known good)
// ---------------------------------------------------------------------------
#define CK 32
#define NCHUNK 4
#define ASTRIDE 36
#define BSTRIDE 136
#define AS_CHUNK (128 * ASTRIDE)
#define BS_CHUNK (CK * BSTRIDE)
#define GEMM_FLOATS (2 * AS_CHUNK + 2 * BS_CHUNK)
#define ROOT_SMEM (GEMM_FLOATS * 4)

__device__ __forceinline__ void compute_chunk(const float* __restrict__ As,
                                              const float* __restrict__ Bs,
                                              int g, int tg, int mw, int nw,
                                              float acc[2][8][4]) {
#pragma unroll
    for (int k0 = 0; k0 < CK; k0 += 8) {
        uint32_t a[2][4];
#pragma unroll
        for (int mi = 0; mi < 2; mi++) {
            const float* Ab = As + (mw * 32 + mi * 16 + g) * ASTRIDE + k0;
            a[mi][0] = __float_as_uint(Ab[tg]);
            a[mi][1] = __float_as_uint(Ab[8 * ASTRIDE + tg]);
            a[mi][2] = __float_as_uint(Ab[tg + 4]);
            a[mi][3] = __float_as_uint(Ab[8 * ASTRIDE + tg + 4]);
        }
        uint32_t b[8][2];
#pragma unroll
        for (int j = 0; j < 8; j++) {
            int col = nw * 64 + 8 * j + g;
            b[j][0] = __float_as_uint(Bs[(k0 + tg) * BSTRIDE + col]);
            b[j][1] = __float_as_uint(Bs[(k0 + tg + 4) * BSTRIDE + col]);
        }
#pragma unroll
        for (int mi = 0; mi < 2; mi++)
#pragma unroll
            for (int j = 0; j < 8; j++)
                mma_tf32(acc[mi][j], a[mi], b[j]);
    }
}

extern "C" __global__ void __launch_bounds__(256, 2)
root_kernel(const float* __restrict__ x, const float* __restrict__ root_b,
            const float* __restrict__ bias, float* __restrict__ out) {
    extern __shared__ float smem[];
    float* Asb[2] = {smem, smem + AS_CHUNK};
    float* Bsb[2] = {smem + 2 * AS_CHUNK, smem + 2 * AS_CHUNK + BS_CHUNK};

    const int tid = threadIdx.x;
    const int n0 = blockIdx.x * 128;

    auto issue = [&](int c, int buf) {
        int k0 = c * CK;
        uint32_t as_base = (uint32_t)__cvta_generic_to_shared(Asb[buf]);
        uint32_t bs_base = (uint32_t)__cvta_generic_to_shared(Bsb[buf]);
#pragma unroll
        for (int it = 0; it < 4; it++) {
            int s = tid + it * 256;
            int row = s >> 3, off = (s & 7) * 4;
            int gr = n0 + row;
            if (gr >= N_NODES) gr = 0;
            cp16(as_base + (row * ASTRIDE + off) * 4, x + (size_t)gr * D + k0 + off);
        }
#pragma unroll
        for (int it = 0; it < 4; it++) {
            int s = tid + it * 256;
            int k = s >> 5, off = (s & 31) * 4;
            cp16(bs_base + (k * BSTRIDE + off) * 4, g_rw + (size_t)(k0 + k) * D + off);
        }
        cp_commit();
    };

    const int lane = tid & 31, warp = tid >> 5;
    const int g = lane >> 2, tg = lane & 3;
    const int mw = warp >> 1, nw = warp & 1;

    float acc[2][8][4];
#pragma unroll
    for (int mi = 0; mi < 2; mi++)
#pragma unroll
        for (int j = 0; j < 8; j++)
#pragma unroll
            for (int c4 = 0; c4 < 4; c4++) acc[mi][j][c4] = 0.f;

    issue(0, 0);
#pragma unroll
    for (int c = 0; c < NCHUNK; c++) {
        if (c + 1 < NCHUNK) { issue(c + 1, (c + 1) & 1); cp_wait<1>(); }
        else cp_wait<0>();
        __syncthreads();
        compute_chunk(Asb[c & 1], Bsb[c & 1], g, tg, mw, nw, acc);
        __syncthreads();
    }

#pragma unroll
    for (int mi = 0; mi < 2; mi++) {
        int row0 = n0 + mw * 32 + mi * 16 + g;
#pragma unroll
        for (int j = 0; j < 8; j++) {
            int col = nw * 64 + 8 * j + 2 * tg;
            float b0 = root_b[col] + bias[col];
            float b1 = root_b[col + 1] + bias[col + 1];
            if (row0 < N_NODES)
                *(float2*)&out[(size_t)row0 * D + col] =
                    make_float2(acc[mi][j][0] + b0, acc[mi][j][1] + b1);
            if (row0 + 8 < N_NODES)
                *(float2*)&out[(size_t)(row0 + 8) * D + col] =
                    make_float2(acc[mi][j][2] + b0, acc[mi][j][3] + b1);
        }
    }
}

// ---------------------------------------------------------------------------
// ReLU
// ---------------------------------------------------------------------------
extern "C" __global__ void relu_kernel(float4* __restrict__ out, int n4) {
    int i = blockIdx.x * blockDim.x + threadIdx.x;
    int stride = gridDim.x * blockDim.x;
    for (; i < n4; i += stride) {
        float4 v = out[i];
        v.x = fmaxf(v.x, 0.f);
        v.y = fmaxf(v.y, 0.f);
        v.z = fmaxf(v.z, 0.f);
        v.w = fmaxf(v.w, 0.f);
        out[i] = v;
    }
}

extern "C" void kernel_launch(void* const* d_in, const int* in_sizes, int n_in,
                              void* d_out, int out_size) {
    const float* x      = (const float*)d_in[0];
    const int*   src    = (const int*)d_in[1];
    const int*   dst    = (const int*)d_in[2];
    const float* ew     = (const float*)d_in[3];
    const float* weight = (const float*)d_in[4];
    const float* root_w = (const float*)d_in[5];
    const float* root_b = (const float*)d_in[6];
    const float* bias   = (const float*)d_in[7];
    float* out = (float*)d_out;

    cudaFuncSetAttribute(root_kernel, cudaFuncAttributeMaxDynamicSharedMemorySize, ROOT_SMEM);
    cudaFuncSetAttribute(edge_kernel, cudaFuncAttributeMaxDynamicSharedMemorySize, EDGE_SMEM);

    pack_w_kernel<<<N_REL + 1, 256>>>(weight, root_w);

    int root_blocks = (N_NODES + 127) / 128;  // 391
    root_kernel<<<root_blocks, 256, ROOT_SMEM>>>(x, root_b, bias, out);

    dim3 egrid(N_EDGE / 128 / TILES_PER_CTA, N_REL);  // 125 x 8 = 1000 CTAs
    edge_kernel<<<egrid, 256, EDGE_SMEM>>>(x, src, dst, ew, out);

    int n4 = out_size / 4;
    relu_kernel<<<1184, 256>>>((float4*)out, n4);
}

// round 8
// speedup vs baseline: 1.1017x; 1.1017x over previous
#include <cuda_runtime.h>
#include <cstdint>

#define N_NODES 50000
#define N_REL 8
#define N_EDGE 64000
#define D 128

// K-chunked pipelined tile: M=128, N=128, K in 4 chunks of 32, double buffered.
#define CK 32
#define ASTRIDE 36                 // conflict-free A-fragment LDS (4g+tg)
#define AS_CHUNK (128 * ASTRIDE)   // 4608 floats per buffer
#define BP_CHUNK 4096              // packed-B chunk: 4 k-steps x 1024 floats
#define CS_STRIDE 132              // C staging stride for scatter

#define GEMM_FLOATS (2 * AS_CHUNK + 2 * BP_CHUNK)   // 17408 floats = 69632 B
#define EDGE_SMEM ((GEMM_FLOATS + 384) * 4)
#define ROOT_SMEM (GEMM_FLOATS * 4)

__device__ __forceinline__ uint32_t f2tf32(float f) {
    uint32_t r;
    asm("cvt.rna.tf32.f32 %0, %1;" : "=r"(r) : "f"(f));
    return r;
}
__device__ __forceinline__ void cp16(uint32_t sa, const float* g) {
    asm volatile("cp.async.cg.shared.global [%0], [%1], 16;" ::"r"(sa), "l"(g));
}
__device__ __forceinline__ void cp_commit() { asm volatile("cp.async.commit_group;"); }
template <int N>
__device__ __forceinline__ void cp_wait() { asm volatile("cp.async.wait_group %0;" ::"n"(N)); }

__device__ __forceinline__ void mma_tf32(float c[4], const uint32_t a[4],
                                         uint32_t b0, uint32_t b1) {
    asm volatile(
        "mma.sync.aligned.m16n8k8.row.col.f32.tf32.tf32.f32 "
        "{%0,%1,%2,%3}, {%4,%5,%6,%7}, {%8,%9}, {%0,%1,%2,%3};\n"
        : "+f"(c[0]), "+f"(c[1]), "+f"(c[2]), "+f"(c[3])
        : "r"(a[0]), "r"(a[1]), "r"(a[2]), "r"(a[3]), "r"(b0), "r"(b1));
}

// ---------------------------------------------------------------------------
// Packed B images: fragment-order layout so each thread's 16 B-floats per
// k-step are one contiguous (XOR-swizzled) 64B block -> 4x LDS.128.
// Logical W[k][n] -> packed addr:
//   k0s=k>>3, h=(k&7)>>2, tg=k&3; nw=n>>6, j=(n&63)>>3, g=n&7
//   lane=g*4+tg, f=2*j+h, u=lane*4+(f>>2)
//   cp=(u&~7)|((u&7)^((u>>3)&7))
//   addr = k0s*1024 + nw*512 + cp*4 + (f&3)
// ---------------------------------------------------------------------------
__device__ float g_wt[N_REL * D * D];
__device__ float g_rw[D * D];

__device__ __forceinline__ int pack_addr(int k, int n) {
    int k0s = k >> 3, r3 = k & 7, h = r3 >> 2, tg = r3 & 3;
    int nw = n >> 6, n64 = n & 63, j = n64 >> 3, g = n64 & 7;
    int lane = g * 4 + tg, f = 2 * j + h;
    int u = lane * 4 + (f >> 2);
    int cp = (u & ~7) | ((u & 7) ^ ((u >> 3) & 7));
    return k0s * 1024 + nw * 512 + cp * 4 + (f & 3);
}

extern "C" __global__ void pack_w_kernel(const float* __restrict__ weight,
                                         const float* __restrict__ root_w) {
    int r = blockIdx.x;
    if (r < N_REL) {
        for (int i = threadIdx.x; i < D * D; i += blockDim.x) {
            int k = i >> 7, n = i & 127;
            g_wt[r * D * D + pack_addr(k, n)] =
                __uint_as_float(f2tf32(weight[r * D * D + i]));
        }
    } else {
        for (int i = threadIdx.x; i < D * D; i += blockDim.x) {
            int k = i >> 7, n = i & 127;
            g_rw[pack_addr(k, n)] = __uint_as_float(f2tf32(root_w[i]));
        }
    }
}

// Compute one K=32 chunk: A raw fp32 (HW tf32 trunc), B packed fragment order.
__device__ __forceinline__ void compute_chunk(const float* __restrict__ As,
                                              const float* __restrict__ Bp,
                                              int g, int tg, int mw, int nw,
                                              const int boff[4],
                                              float acc[2][8][4]) {
#pragma unroll
    for (int s = 0; s < 4; s++) {
        const int k0 = s * 8;
        uint32_t a[2][4];
#pragma unroll
        for (int mi = 0; mi < 2; mi++) {
            const float* Ab = As + (mw * 32 + mi * 16 + g) * ASTRIDE + k0;
            a[mi][0] = __float_as_uint(Ab[tg]);
            a[mi][1] = __float_as_uint(Ab[8 * ASTRIDE + tg]);
            a[mi][2] = __float_as_uint(Ab[tg + 4]);
            a[mi][3] = __float_as_uint(Ab[8 * ASTRIDE + tg + 4]);
        }
        uint32_t bf[16];
        const float* Bk = Bp + s * 1024 + nw * 512;
#pragma unroll
        for (int j = 0; j < 4; j++) {
            float4 v = *(const float4*)(Bk + boff[j]);
            bf[4 * j + 0] = __float_as_uint(v.x);
            bf[4 * j + 1] = __float_as_uint(v.y);
            bf[4 * j + 2] = __float_as_uint(v.z);
            bf[4 * j + 3] = __float_as_uint(v.w);
        }
#pragma unroll
        for (int mi = 0; mi < 2; mi++)
#pragma unroll
            for (int j2 = 0; j2 < 8; j2++)
                mma_tf32(acc[mi][j2], a[mi], bf[2 * j2], bf[2 * j2 + 1]);
    }
}

// per-thread packed-B 16B-unit offsets (floats), constant across chunks
__device__ __forceinline__ void make_boff(int lane, int boff[4]) {
    int lh = lane >> 1, sel = (lane & 1) * 4, x7 = lh & 7;
#pragma unroll
    for (int j = 0; j < 4; j++) boff[j] = (lh * 8 + ((sel + j) ^ x7)) * 4;
}

// ---------------------------------------------------------------------------
// Kernel 1: out = x @ root_w + root_b + bias (dense init of all rows)
// ---------------------------------------------------------------------------
extern "C" __global__ void __launch_bounds__(256, 2)
root_kernel(const float* __restrict__ x, const float* __restrict__ root_b,
            const float* __restrict__ bias, float* __restrict__ out) {
    extern __shared__ float smem[];
    float* Asb[2] = {smem, smem + AS_CHUNK};
    float* Bsb[2] = {smem + 2 * AS_CHUNK, smem + 2 * AS_CHUNK + BP_CHUNK};

    const int tid = threadIdx.x;
    const int n0 = blockIdx.x * 128;

    auto issue = [&](int c, int buf) {
        uint32_t as_base = (uint32_t)__cvta_generic_to_shared(Asb[buf]);
        uint32_t bs_base = (uint32_t)__cvta_generic_to_shared(Bsb[buf]);
#pragma unroll
        for (int it = 0; it < 4; it++) {
            int s = tid + it * 256;
            int row = s >> 3, off = (s & 7) * 4;
            int gr = n0 + row;
            if (gr >= N_NODES) gr = 0;
            cp16(as_base + (row * ASTRIDE + off) * 4, x + (size_t)gr * D + c * CK + off);
        }
#pragma unroll
        for (int it = 0; it < 4; it++) {
            int j16 = tid + it * 256;
            cp16(bs_base + j16 * 16, g_rw + c * BP_CHUNK + j16 * 4);
        }
        cp_commit();
    };

    const int lane = tid & 31, warp = tid >> 5;
    const int g = lane >> 2, tg = lane & 3;
    const int mw = warp >> 1, nw = warp & 1;
    int boff[4];
    make_boff(lane, boff);

    float acc[2][8][4];
#pragma unroll
    for (int mi = 0; mi < 2; mi++)
#pragma unroll
        for (int j = 0; j < 8; j++)
#pragma unroll
            for (int c4 = 0; c4 < 4; c4++) acc[mi][j][c4] = 0.f;

    issue(0, 0);
#pragma unroll
    for (int c = 0; c < 4; c++) {
        cp_wait<0>();
        __syncthreads();  // chunk c arrived; all warps done with buffer c^1
        if (c + 1 < 4) issue(c + 1, (c + 1) & 1);
        compute_chunk(Asb[c & 1], Bsb[c & 1], g, tg, mw, nw, boff, acc);
    }

#pragma unroll
    for (int mi = 0; mi < 2; mi++) {
        int row0 = n0 + mw * 32 + mi * 16 + g;
#pragma unroll
        for (int j = 0; j < 8; j++) {
            int col = nw * 64 + 8 * j + 2 * tg;
            float b0 = root_b[col] + bias[col];
            float b1 = root_b[col + 1] + bias[col + 1];
            if (row0 < N_NODES)
                *(float2*)&out[(size_t)row0 * D + col] =
                    make_float2(acc[mi][j][0] + b0, acc[mi][j][1] + b1);
            if (row0 + 8 < N_NODES)
                *(float2*)&out[(size_t)(row0 + 8) * D + col] =
                    make_float2(acc[mi][j][2] + b0, acc[mi][j][3] + b1);
        }
    }
}

// ---------------------------------------------------------------------------
// Kernel 2: per-relation edge tiles: gather x[src] -> GEMM W_r -> *ew ->
//           red.v4 atomic scatter into out[dst]
// ---------------------------------------------------------------------------
extern "C" __global__ void __launch_bounds__(256, 2)
edge_kernel(const float* __restrict__ x, const int* __restrict__ src,
            const int* __restrict__ dst, const float* __restrict__ ew,
            float* __restrict__ out) {
    extern __shared__ float smem[];
    float* Asb[2] = {smem, smem + AS_CHUNK};
    float* Bsb[2] = {smem + 2 * AS_CHUNK, smem + 2 * AS_CHUNK + BP_CHUNK};
    int* s_src = (int*)(smem + GEMM_FLOATS);
    int* s_dst = s_src + 128;
    float* s_ew = (float*)(s_dst + 128);

    const int tid = threadIdx.x;
    const int r = blockIdx.y;
    const int e0 = blockIdx.x * 128;
    const int ebase = r * N_EDGE + e0;
    const float* W = g_wt + (size_t)r * D * D;

    if (tid < 128) {
        s_src[tid] = src[ebase + tid];
        s_dst[tid] = dst[ebase + tid];
        s_ew[tid] = ew[ebase + tid];
    }
    __syncthreads();

    auto issue = [&](int c, int buf) {
        uint32_t as_base = (uint32_t)__cvta_generic_to_shared(Asb[buf]);
        uint32_t bs_base = (uint32_t)__cvta_generic_to_shared(Bsb[buf]);
#pragma unroll
        for (int it = 0; it < 4; it++) {
            int s = tid + it * 256;
            int row = s >> 3, off = (s & 7) * 4;
            cp16(as_base + (row * ASTRIDE + off) * 4,
                 x + (size_t)s_src[row] * D + c * CK + off);
        }
#pragma unroll
        for (int it = 0; it < 4; it++) {
            int j16 = tid + it * 256;
            cp16(bs_base + j16 * 16, W + c * BP_CHUNK + j16 * 4);
        }
        cp_commit();
    };

    const int lane = tid & 31, warp = tid >> 5;
    const int g = lane >> 2, tg = lane & 3;
    const int mw = warp >> 1, nw = warp & 1;
    int boff[4];
    make_boff(lane, boff);

    float acc[2][8][4];
#pragma unroll
    for (int mi = 0; mi < 2; mi++)
#pragma unroll
        for (int j = 0; j < 8; j++)
#pragma unroll
            for (int c4 = 0; c4 < 4; c4++) acc[mi][j][c4] = 0.f;

    issue(0, 0);
#pragma unroll
    for (int c = 0; c < 4; c++) {
        cp_wait<0>();
        __syncthreads();  // chunk c arrived; all warps done with buffer c^1
        if (c + 1 < 4) issue(c + 1, (c + 1) & 1);
        compute_chunk(Asb[c & 1], Bsb[c & 1], g, tg, mw, nw, boff, acc);
    }
    __syncthreads();  // all warps done reading smem; safe to overlay C

    // stage scaled C into smem (overlay pipeline buffers) for 128-bit REDs
    float* Cs = smem;  // 128 * 132 = 16896 <= GEMM_FLOATS; idx arrays safe
#pragma unroll
    for (int mi = 0; mi < 2; mi++) {
        int row0 = mw * 32 + mi * 16 + g;
        float w0 = s_ew[row0], w1 = s_ew[row0 + 8];
#pragma unroll
        for (int j = 0; j < 8; j++) {
            int col = nw * 64 + 8 * j + 2 * tg;
            *(float2*)&Cs[row0 * CS_STRIDE + col] =
                make_float2(acc[mi][j][0] * w0, acc[mi][j][1] * w0);
            *(float2*)&Cs[(row0 + 8) * CS_STRIDE + col] =
                make_float2(acc[mi][j][2] * w1, acc[mi][j][3] * w1);
        }
    }
    __syncthreads();

#pragma unroll
    for (int it = 0; it < 16; it++) {
        int t = tid + it * 256;
        int row = t >> 5, q = t & 31;
        const float4 v = *(const float4*)&Cs[row * CS_STRIDE + q * 4];
        float* p = out + (size_t)s_dst[row] * D + q * 4;
        asm volatile("red.global.add.v4.f32 [%0], {%1,%2,%3,%4};"
                     ::"l"(p), "f"(v.x), "f"(v.y), "f"(v.z), "f"(v.w)
                     : "memory");
    }
}

// ---------------------------------------------------------------------------
// Kernel 3: in-place ReLU
// ---------------------------------------------------------------------------
extern "C" __global__ void relu_kernel(float4* __restrict__ out, int n4) {
    int i = blockIdx.x * blockDim.x + threadIdx.x;
    int stride = gridDim.x * blockDim.x;
    for (; i < n4; i += stride) {
        float4 v = out[i];
        v.x = fmaxf(v.x, 0.f);
        v.y = fmaxf(v.y, 0.f);
        v.z = fmaxf(v.z, 0.f);
        v.w = fmaxf(v.w, 0.f);
        out[i] = v;
    }
}

extern "C" void kernel_launch(void* const* d_in, const int* in_sizes, int n_in,
                              void* d_out, int out_size) {
    const float* x      = (const float*)d_in[0];
    const int*   src    = (const int*)d_in[1];
    const int*   dst    = (const int*)d_in[2];
    const float* ew     = (const float*)d_in[3];
    const float* weight = (const float*)d_in[4];
    const float* root_w = (const float*)d_in[5];
    const float* root_b = (const float*)d_in[6];
    const float* bias   = (const float*)d_in[7];
    float* out = (float*)d_out;

    cudaFuncSetAttribute(root_kernel, cudaFuncAttributeMaxDynamicSharedMemorySize, ROOT_SMEM);
    cudaFuncSetAttribute(edge_kernel, cudaFuncAttributeMaxDynamicSharedMemorySize, EDGE_SMEM);

    pack_w_kernel<<<N_REL + 1, 256>>>(weight, root_w);

    int root_blocks = (N_NODES + 127) / 128;  // 391
    root_kernel<<<root_blocks, 256, ROOT_SMEM>>>(x, root_b, bias, out);

    dim3 egrid(N_EDGE / 128, N_REL);  // 500 x 8
    edge_kernel<<<egrid, 256, EDGE_SMEM>>>(x, src, dst, ew, out);

    int n4 = out_size / 4;
    relu_kernel<<<1184, 256>>>((float4*)out, n4);
}

// round 11
// speedup vs baseline: 1.1394x; 1.0343x over previous
#include <cuda_runtime.h>
#include <cstdint>

#define N_NODES 50000
#define N_REL 8
#define N_EDGE 64000
#define D 128

#define CK 32
#define A_STRIDE 132                 // floats; 528B rows, 16B-aligned, conflict-free
#define A_FLOATS (128 * A_STRIDE)    // 16896 floats = 67584 B
#define BP_CHUNK 4096                // packed-B chunk floats (16 KB)
#define CS_STRIDE 132

// smem float layout: A[16896] | B0[4096] | B1[4096] | mbar[3]*2 | s_dst[128] | s_ew[128]
#define MB_OFF (A_FLOATS + 2 * BP_CHUNK)        // 25088
#define SDST_OFF (MB_OFF + 8)
#define SEW_OFF (SDST_OFF + 128)
#define SMEM_FLOATS (SEW_OFF + 128)
#define EDGE_SMEM (SMEM_FLOATS * 4)              // 101,408 B -> 2 CTAs/SM
#define ROOT_SMEM ((MB_OFF + 8) * 4)

__device__ __forceinline__ uint32_t f2tf32(float f) {
    uint32_t r;
    asm("cvt.rna.tf32.f32 %0, %1;" : "=r"(r) : "f"(f));
    return r;
}

#define MBAR_INIT(mb, c) asm volatile("mbarrier.init.shared.b64 [%0], %1;" ::"r"(mb), "r"(c) : "memory")
#define MBAR_EXPECT(mb, bytes) asm volatile("mbarrier.arrive.expect_tx.shared.b64 _, [%0], %1;" ::"r"(mb), "r"(bytes) : "memory")

__device__ __forceinline__ void bulk_cp(uint32_t dst, const void* src, uint32_t bytes, uint32_t mb) {
    asm volatile(
        "cp.async.bulk.shared::cta.global.mbarrier::complete_tx::bytes [%0], [%1], %2, [%3];"
        ::"r"(dst), "l"(src), "r"(bytes), "r"(mb) : "memory");
}

// Bounded parity wait (~0.1s max): a protocol bug becomes a fast rel_err
// failure instead of a dead container.
__device__ __forceinline__ void mbar_wait(uint32_t mb, uint32_t parity) {
    for (int i = 0; i < (1 << 21); i++) {
        uint32_t done;
        asm volatile(
            "{\n\t.reg .pred p;\n\t"
            "mbarrier.try_wait.parity.acquire.cta.shared::cta.b64 p, [%1], %2;\n\t"
            "selp.b32 %0, 1, 0, p;\n\t}"
            : "=r"(done) : "r"(mb), "r"(parity) : "memory");
        if (done) return;
    }
}

__device__ __forceinline__ void mma_tf32(float c[4], const uint32_t a[4],
                                         uint32_t b0, uint32_t b1) {
    asm volatile(
        "mma.sync.aligned.m16n8k8.row.col.f32.tf32.tf32.f32 "
        "{%0,%1,%2,%3}, {%4,%5,%6,%7}, {%8,%9}, {%0,%1,%2,%3};\n"
        : "+f"(c[0]), "+f"(c[1]), "+f"(c[2]), "+f"(c[3])
        : "r"(a[0]), "r"(a[1]), "r"(a[2]), "r"(a[3]), "r"(b0), "r"(b1));
}

// ---------------------------------------------------------------------------
// Packed B images (fragment order, XOR-swizzled 64B blocks) — same as R8.
// ---------------------------------------------------------------------------
__device__ float g_wt[N_REL * D * D];
__device__ float g_rw[D * D];

__device__ __forceinline__ int pack_addr(int k, int n) {
    int k0s = k >> 3, r3 = k & 7, h = r3 >> 2, tg = r3 & 3;
    int nw = n >> 6, n64 = n & 63, j = n64 >> 3, g = n64 & 7;
    int lane = g * 4 + tg, f = 2 * j + h;
    int u = lane * 4 + (f >> 2);
    int cp = (u & ~7) | ((u & 7) ^ ((u >> 3) & 7));
    return k0s * 1024 + nw * 512 + cp * 4 + (f & 3);
}

extern "C" __global__ void pack_w_kernel(const float* __restrict__ weight,
                                         const float* __restrict__ root_w) {
    int r = blockIdx.x;
    if (r < N_REL) {
        for (int i = threadIdx.x; i < D * D; i += blockDim.x) {
            int k = i >> 7, n = i & 127;
            g_wt[r * D * D + pack_addr(k, n)] =
                __uint_as_float(f2tf32(weight[r * D * D + i]));
        }
    } else {
        for (int i = threadIdx.x; i < D * D; i += blockDim.x) {
            int k = i >> 7, n = i & 127;
            g_rw[pack_addr(k, n)] = __uint_as_float(f2tf32(root_w[i]));
        }
    }
}

// per-thread packed-B 16B-unit offsets (floats), constant across chunks
__device__ __forceinline__ void make_boff(int lane, int boff[4]) {
    int lh = lane >> 1, sel = (lane & 1) * 4, x7 = lh & 7;
#pragma unroll
    for (int j = 0; j < 4; j++) boff[j] = (lh * 8 + ((sel + j) ^ x7)) * 4;
}

// Compute one K=32 chunk: A raw fp32 (stride A_STRIDE), B packed fragment order.
__device__ __forceinline__ void compute_chunk(const float* __restrict__ As,
                                              const float* __restrict__ Bp,
                                              int g, int tg, int mw, int nw,
                                              const int boff[4], int cbase,
                                              float acc[2][8][4]) {
#pragma unroll
    for (int s = 0; s < 4; s++) {
        const int k0 = cbase + s * 8;
        uint32_t a[2][4];
#pragma unroll
        for (int mi = 0; mi < 2; mi++) {
            const float* Ab = As + (mw * 32 + mi * 16 + g) * A_STRIDE + k0;
            a[mi][0] = __float_as_uint(Ab[tg]);
            a[mi][1] = __float_as_uint(Ab[8 * A_STRIDE + tg]);
            a[mi][2] = __float_as_uint(Ab[tg + 4]);
            a[mi][3] = __float_as_uint(Ab[8 * A_STRIDE + tg + 4]);
        }
        uint32_t bf[16];
        const float* Bk = Bp + s * 1024 + nw * 512;
#pragma unroll
        for (int j = 0; j < 4; j++) {
            float4 v = *(const float4*)(Bk + boff[j]);
            bf[4 * j + 0] = __float_as_uint(v.x);
            bf[4 * j + 1] = __float_as_uint(v.y);
            bf[4 * j + 2] = __float_as_uint(v.z);
            bf[4 * j + 3] = __float_as_uint(v.w);
        }
#pragma unroll
        for (int mi = 0; mi < 2; mi++)
#pragma unroll
            for (int j2 = 0; j2 < 8; j2++)
                mma_tf32(acc[mi][j2], a[mi], bf[2 * j2], bf[2 * j2 + 1]);
    }
}

// ---------------------------------------------------------------------------
// Kernel 1: out = x @ root_w + root_b + bias
// ---------------------------------------------------------------------------
extern "C" __global__ void __launch_bounds__(256, 2)
root_kernel(const float* __restrict__ x, const float* __restrict__ root_b,
            const float* __restrict__ bias, float* __restrict__ out) {
    extern __shared__ float smem[];
    float* As = smem;
    float* Bsb[2] = {smem + A_FLOATS, smem + A_FLOATS + BP_CHUNK};

    const int tid = threadIdx.x;
    const int n0 = blockIdx.x * 128;
    const uint32_t sb = (uint32_t)__cvta_generic_to_shared(smem);
    const uint32_t mbA = sb + MB_OFF * 4, mbB0 = mbA + 8, mbB1 = mbA + 16;
    const uint32_t a_base = sb;
    const uint32_t b_base[2] = {sb + A_FLOATS * 4, sb + (A_FLOATS + BP_CHUNK) * 4};

    if (tid == 0) { MBAR_INIT(mbA, 1); MBAR_INIT(mbB0, 1); MBAR_INIT(mbB1, 1); }
    __syncthreads();

    if (tid == 0) {
        MBAR_EXPECT(mbA, 128 * 512);
        MBAR_EXPECT(mbB0, 16384);
        MBAR_EXPECT(mbB1, 16384);
        bulk_cp(b_base[0], g_rw, 16384, mbB0);
        bulk_cp(b_base[1], g_rw + BP_CHUNK, 16384, mbB1);
    }
    if (tid < 128) {
        int gr = n0 + tid;
        if (gr >= N_NODES) gr = 0;
        bulk_cp(a_base + tid * (A_STRIDE * 4), x + (size_t)gr * D, 512, mbA);
    }

    const int lane = tid & 31, warp = tid >> 5;
    const int g = lane >> 2, tg = lane & 3;
    const int mw = warp >> 1, nw = warp & 1;
    int boff[4];
    make_boff(lane, boff);

    float acc[2][8][4];
#pragma unroll
    for (int mi = 0; mi < 2; mi++)
#pragma unroll
        for (int j = 0; j < 8; j++)
#pragma unroll
            for (int c4 = 0; c4 < 4; c4++) acc[mi][j][c4] = 0.f;

#pragma unroll
    for (int c = 0; c < 4; c++) {
        if (c == 0) mbar_wait(mbA, 0);
        mbar_wait(c & 1 ? mbB1 : mbB0, c >> 1);
        compute_chunk(As, Bsb[c & 1], g, tg, mw, nw, boff, c * CK, acc);
        __syncthreads();
        if (c + 2 < 4 && tid == 0) {
            uint32_t mb = (c & 1) ? mbB1 : mbB0;
            MBAR_EXPECT(mb, 16384);
            bulk_cp(b_base[c & 1], g_rw + (c + 2) * BP_CHUNK, 16384, mb);
        }
    }

#pragma unroll
    for (int mi = 0; mi < 2; mi++) {
        int row0 = n0 + mw * 32 + mi * 16 + g;
#pragma unroll
        for (int j = 0; j < 8; j++) {
            int col = nw * 64 + 8 * j + 2 * tg;
            float b0 = root_b[col] + bias[col];
            float b1 = root_b[col + 1] + bias[col + 1];
            if (row0 < N_NODES)
                *(float2*)&out[(size_t)row0 * D + col] =
                    make_float2(acc[mi][j][0] + b0, acc[mi][j][1] + b1);
            if (row0 + 8 < N_NODES)
                *(float2*)&out[(size_t)(row0 + 8) * D + col] =
                    make_float2(acc[mi][j][2] + b0, acc[mi][j][3] + b1);
        }
    }
}

// ---------------------------------------------------------------------------
// Kernel 2: edge tiles — bulk-copy gather, GEMM, *ew, red.v4 scatter
// ---------------------------------------------------------------------------
extern "C" __global__ void __launch_bounds__(256, 2)
edge_kernel(const float* __restrict__ x, const int* __restrict__ src,
            const int* __restrict__ dst, const float* __restrict__ ew,
            float* __restrict__ out) {
    extern __shared__ float smem[];
    float* As = smem;
    float* Bsb[2] = {smem + A_FLOATS, smem + A_FLOATS + BP_CHUNK};
    int* s_dst = (int*)(smem + SDST_OFF);
    float* s_ew = smem + SEW_OFF;

    const int tid = threadIdx.x;
    const int r = blockIdx.y;
    const int ebase = r * N_EDGE + blockIdx.x * 128;
    const float* W = g_wt + (size_t)r * D * D;

    const uint32_t sb = (uint32_t)__cvta_generic_to_shared(smem);
    const uint32_t mbA = sb + MB_OFF * 4, mbB0 = mbA + 8, mbB1 = mbA + 16;
    const uint32_t a_base = sb;
    const uint32_t b_base[2] = {sb + A_FLOATS * 4, sb + (A_FLOATS + BP_CHUNK) * 4};

    if (tid == 0) { MBAR_INIT(mbA, 1); MBAR_INIT(mbB0, 1); MBAR_INIT(mbB1, 1); }
    __syncthreads();

    if (tid == 0) {
        MBAR_EXPECT(mbA, 128 * 512);
        MBAR_EXPECT(mbB0, 16384);
        MBAR_EXPECT(mbB1, 16384);
        bulk_cp(b_base[0], W, 16384, mbB0);
        bulk_cp(b_base[1], W + BP_CHUNK, 16384, mbB1);
    }
    if (tid < 128) {
        int srow = __ldg(&src[ebase + tid]);
        bulk_cp(a_base + tid * (A_STRIDE * 4), x + (size_t)srow * D, 512, mbA);
        s_dst[tid] = __ldg(&dst[ebase + tid]);
        s_ew[tid] = __ldg(&ew[ebase + tid]);
    }

    const int lane = tid & 31, warp = tid >> 5;
    const int g = lane >> 2, tg = lane & 3;
    const int mw = warp >> 1, nw = warp & 1;
    int boff[4];
    make_boff(lane, boff);

    float acc[2][8][4];
#pragma unroll
    for (int mi = 0; mi < 2; mi++)
#pragma unroll
        for (int j = 0; j < 8; j++)
#pragma unroll
            for (int c4 = 0; c4 < 4; c4++) acc[mi][j][c4] = 0.f;

#pragma unroll
    for (int c = 0; c < 4; c++) {
        if (c == 0) mbar_wait(mbA, 0);
        mbar_wait(c & 1 ? mbB1 : mbB0, c >> 1);
        compute_chunk(As, Bsb[c & 1], g, tg, mw, nw, boff, c * CK, acc);
        __syncthreads();
        if (c + 2 < 4 && tid == 0) {
            uint32_t mb = (c & 1) ? mbB1 : mbB0;
            MBAR_EXPECT(mb, 16384);
            bulk_cp(b_base[c & 1], W + (c + 2) * BP_CHUNK, 16384, mb);
        }
    }

    // stage scaled C into the A buffer (all compute done; sync above)
    float* Cs = As;
#pragma unroll
    for (int mi = 0; mi < 2; mi++) {
        int row0 = mw * 32 + mi * 16 + g;
        float w0 = s_ew[row0], w1 = s_ew[row0 + 8];
#pragma unroll
        for (int j = 0; j < 8; j++) {
            int col = nw * 64 + 8 * j + 2 * tg;
            *(float2*)&Cs[row0 * CS_STRIDE + col] =
                make_float2(acc[mi][j][0] * w0, acc[mi][j][1] * w0);
            *(float2*)&Cs[(row0 + 8) * CS_STRIDE + col] =
                make_float2(acc[mi][j][2] * w1, acc[mi][j][3] * w1);
        }
    }
    __syncthreads();

#pragma unroll
    for (int it = 0; it < 16; it++) {
        int t = tid + it * 256;
        int row = t >> 5, q = t & 31;
        const float4 v = *(const float4*)&Cs[row * CS_STRIDE + q * 4];
        float* p = out + (size_t)s_dst[row] * D + q * 4;
        asm volatile("red.global.add.v4.f32 [%0], {%1,%2,%3,%4};"
                     ::"l"(p), "f"(v.x), "f"(v.y), "f"(v.z), "f"(v.w)
                     : "memory");
    }
}

// ---------------------------------------------------------------------------
// Kernel 3: in-place ReLU
// ---------------------------------------------------------------------------
extern "C" __global__ void relu_kernel(float4* __restrict__ out, int n4) {
    int i = blockIdx.x * blockDim.x + threadIdx.x;
    int stride = gridDim.x * blockDim.x;
    for (; i < n4; i += stride) {
        float4 v = out[i];
        v.x = fmaxf(v.x, 0.f);
        v.y = fmaxf(v.y, 0.f);
        v.z = fmaxf(v.z, 0.f);
        v.w = fmaxf(v.w, 0.f);
        out[i] = v;
    }
}

extern "C" void kernel_launch(void* const* d_in, const int* in_sizes, int n_in,
                              void* d_out, int out_size) {
    const float* x      = (const float*)d_in[0];
    const int*   src    = (const int*)d_in[1];
    const int*   dst    = (const int*)d_in[2];
    const float* ew     = (const float*)d_in[3];
    const float* weight = (const float*)d_in[4];
    const float* root_w = (const float*)d_in[5];
    const float* root_b = (const float*)d_in[6];
    const float* bias   = (const float*)d_in[7];
    float* out = (float*)d_out;

    cudaFuncSetAttribute(root_kernel, cudaFuncAttributeMaxDynamicSharedMemorySize, ROOT_SMEM);
    cudaFuncSetAttribute(edge_kernel, cudaFuncAttributeMaxDynamicSharedMemorySize, EDGE_SMEM);

    pack_w_kernel<<<N_REL + 1, 256>>>(weight, root_w);

    int root_blocks = (N_NODES + 127) / 128;  // 391
    root_kernel<<<root_blocks, 256, ROOT_SMEM>>>(x, root_b, bias, out);

    dim3 egrid(N_EDGE / 128, N_REL);  // 500 x 8
    edge_kernel<<<egrid, 256, EDGE_SMEM>>>(x, src, dst, ew, out);

    int n4 = out_size / 4;
    relu_kernel<<<1184, 256>>>((float4*)out, n4);
}

// round 13
// speedup vs baseline: 1.3019x; 1.1426x over previous
#include <cuda_runtime.h>
#include <cuda_fp16.h>
#include <cstdint>

#define N_NODES 50000
#define N_REL 8
#define N_EDGE 64000
#define D 128

#define A_RB 272                      // bytes per A row in smem (16B mult; conflict-free)
#define A_BYTES (128 * A_RB)          // 34816
#define B_BYTES 32768                 // packed fp16 W image
#define CS_STRIDE 132                 // fp32 C staging stride
#define MB_BYTE (A_BYTES + B_BYTES)   // 67584 == 128*132*4 (C staging fits exactly)
#define SDST_BYTE (MB_BYTE + 16)
#define SEW_BYTE (SDST_BYTE + 512)
#define EDGE_SMEM (SEW_BYTE + 512)    // 68624 B -> 2 CTAs/SM
#define ROOT_SMEM (MB_BYTE + 16)

// fp16 images (static device scratch; no runtime allocation)
__device__ __align__(256) __half g_xh[N_NODES * D];          // 12.8 MB
__device__ __align__(128) __half g_wth[N_REL * D * D];       // packed fragment order
__device__ __align__(128) __half g_rwh[D * D];

#define MBAR_INIT(mb, c) asm volatile("mbarrier.init.shared.b64 [%0], %1;" ::"r"(mb), "r"(c) : "memory")
#define MBAR_EXPECT(mb, bytes) asm volatile("mbarrier.arrive.expect_tx.shared.b64 _, [%0], %1;" ::"r"(mb), "r"(bytes) : "memory")

__device__ __forceinline__ void bulk_cp(uint32_t dst, const void* src, uint32_t bytes, uint32_t mb) {
    asm volatile(
        "cp.async.bulk.shared::cta.global.mbarrier::complete_tx::bytes [%0], [%1], %2, [%3];"
        ::"r"(dst), "l"(src), "r"(bytes), "r"(mb) : "memory");
}

// Bounded parity wait: protocol bug -> fast wrong answer, never a hung container.
__device__ __forceinline__ void mbar_wait(uint32_t mb, uint32_t parity) {
    for (int i = 0; i < (1 << 21); i++) {
        uint32_t done;
        asm volatile(
            "{\n\t.reg .pred p;\n\t"
            "mbarrier.try_wait.parity.acquire.cta.shared::cta.b64 p, [%1], %2;\n\t"
            "selp.b32 %0, 1, 0, p;\n\t}"
            : "=r"(done) : "r"(mb), "r"(parity) : "memory");
        if (done) return;
    }
}

__device__ __forceinline__ void mma_f16(float c[4], const uint32_t a[4],
                                        uint32_t b0, uint32_t b1) {
    asm volatile(
        "mma.sync.aligned.m16n8k16.row.col.f32.f16.f16.f32 "
        "{%0,%1,%2,%3}, {%4,%5,%6,%7}, {%8,%9}, {%0,%1,%2,%3};\n"
        : "+f"(c[0]), "+f"(c[1]), "+f"(c[2]), "+f"(c[3])
        : "r"(a[0]), "r"(a[1]), "r"(a[2]), "r"(a[3]), "r"(b0), "r"(b1));
}

// ---------------------------------------------------------------------------
// x -> fp16 conversion (8 floats / thread, 16B stores)
// ---------------------------------------------------------------------------
__device__ __forceinline__ uint32_t f2h2(float a, float b) {
    __half2 h = __floats2half2_rn(a, b);
    return *(uint32_t*)&h;
}

extern "C" __global__ void xconv_kernel(const float4* __restrict__ x) {
    int i = blockIdx.x * blockDim.x + threadIdx.x;            // one per 8 floats
    const int n8 = N_NODES * D / 8;
    if (i < n8) {
        float4 a = x[2 * i], b = x[2 * i + 1];
        uint4 u;
        u.x = f2h2(a.x, a.y);
        u.y = f2h2(a.z, a.w);
        u.z = f2h2(b.x, b.y);
        u.w = f2h2(b.z, b.w);
        *(uint4*)&g_xh[i * 8] = u;
    }
}

// ---------------------------------------------------------------------------
// W pack: fragment-order fp16 image.
// b32 unit for (k,n): s=k>>4, kl=k&15, r=kl>>3, tg=(kl>>1)&3, hi=kl&1;
// nw=n>>6, j=(n&63)>>3, g=n&7; lane=g*4+tg; f=2j+r; u=lane*4+(f>>2);
// cp=(u&~7)|((u&7)^((u>>3)&7)); b32 = s*1024+nw*512+cp*4+(f&3); half=b32*2+hi
// ---------------------------------------------------------------------------
__device__ __forceinline__ int pack_half_idx(int k, int n) {
    int s = k >> 4, kl = k & 15, r = kl >> 3, tg = (kl >> 1) & 3, hi = kl & 1;
    int nw = n >> 6, j = (n & 63) >> 3, g = n & 7;
    int lane = g * 4 + tg, f = 2 * j + r;
    int u = lane * 4 + (f >> 2);
    int cp = (u & ~7) | ((u & 7) ^ ((u >> 3) & 7));
    return (s * 1024 + nw * 512 + cp * 4 + (f & 3)) * 2 + hi;
}

extern "C" __global__ void pack_w_kernel(const float* __restrict__ weight,
                                         const float* __restrict__ root_w) {
    int r = blockIdx.x;
    if (r < N_REL) {
        for (int i = threadIdx.x; i < D * D; i += blockDim.x) {
            int k = i >> 7, n = i & 127;
            g_wth[r * D * D + pack_half_idx(k, n)] = __float2half_rn(weight[r * D * D + i]);
        }
    } else {
        for (int i = threadIdx.x; i < D * D; i += blockDim.x) {
            int k = i >> 7, n = i & 127;
            g_rwh[pack_half_idx(k, n)] = __float2half_rn(root_w[i]);
        }
    }
}

// per-thread packed-B 16B-unit offsets (b32 units), constant across k-steps
__device__ __forceinline__ void make_boff(int lane, int boff[4]) {
    int lh = lane >> 1, sel = (lane & 1) * 4, x7 = lh & 7;
#pragma unroll
    for (int j = 0; j < 4; j++) boff[j] = (lh * 8 + ((sel + j) ^ x7)) * 4;
}

// full K=128 mainloop: 8 fp16 k16-steps
__device__ __forceinline__ void compute_tile(const char* __restrict__ As,
                                             const uint32_t* __restrict__ Bu,
                                             int g, int tg, int mw, int nw,
                                             const int boff[4],
                                             float acc[2][8][4]) {
#pragma unroll
    for (int s = 0; s < 8; s++) {
        uint32_t a[2][4];
#pragma unroll
        for (int mi = 0; mi < 2; mi++) {
            const char* Ar = As + (mw * 32 + mi * 16 + g) * A_RB + s * 32 + tg * 4;
            a[mi][0] = *(const uint32_t*)Ar;
            a[mi][1] = *(const uint32_t*)(Ar + 8 * A_RB);
            a[mi][2] = *(const uint32_t*)(Ar + 16);
            a[mi][3] = *(const uint32_t*)(Ar + 8 * A_RB + 16);
        }
        uint32_t bf[16];
        const uint32_t* Bk = Bu + s * 1024 + nw * 512;
#pragma unroll
        for (int j4 = 0; j4 < 4; j4++) {
            uint4 v = *(const uint4*)(Bk + boff[j4]);
            bf[4 * j4 + 0] = v.x;
            bf[4 * j4 + 1] = v.y;
            bf[4 * j4 + 2] = v.z;
            bf[4 * j4 + 3] = v.w;
        }
#pragma unroll
        for (int mi = 0; mi < 2; mi++)
#pragma unroll
            for (int j = 0; j < 8; j++)
                mma_f16(acc[mi][j], a[mi], bf[2 * j], bf[2 * j + 1]);
    }
}

// ---------------------------------------------------------------------------
// Kernel: root = x @ root_w + root_b + bias (dense init)
// ---------------------------------------------------------------------------
extern "C" __global__ void __launch_bounds__(256, 2)
root_kernel(const float* __restrict__ root_b, const float* __restrict__ bias,
            float* __restrict__ out) {
    extern __shared__ char smem[];
    const uint32_t sb = (uint32_t)__cvta_generic_to_shared(smem);
    const char* As = smem;
    const uint32_t* Bu = (const uint32_t*)(smem + A_BYTES);
    const uint32_t mbA = sb + MB_BYTE, mbB = mbA + 8;

    const int tid = threadIdx.x;
    const int n0 = blockIdx.x * 128;

    if (tid == 0) { MBAR_INIT(mbA, 1); MBAR_INIT(mbB, 1); }
    __syncthreads();
    if (tid == 0) {
        MBAR_EXPECT(mbA, 128 * 256);
        MBAR_EXPECT(mbB, B_BYTES);
        bulk_cp(sb + A_BYTES, g_rwh, B_BYTES, mbB);
    }
    if (tid < 128) {
        int gr = n0 + tid;
        if (gr >= N_NODES) gr = 0;
        bulk_cp(sb + tid * A_RB, g_xh + (size_t)gr * D, 256, mbA);
    }

    const int lane = tid & 31, warp = tid >> 5;
    const int g = lane >> 2, tg = lane & 3;
    const int mw = warp >> 1, nw = warp & 1;
    int boff[4];
    make_boff(lane, boff);

    float acc[2][8][4];
#pragma unroll
    for (int mi = 0; mi < 2; mi++)
#pragma unroll
        for (int j = 0; j < 8; j++)
#pragma unroll
            for (int c4 = 0; c4 < 4; c4++) acc[mi][j][c4] = 0.f;

    mbar_wait(mbA, 0);
    mbar_wait(mbB, 0);
    compute_tile(As, Bu, g, tg, mw, nw, boff, acc);

#pragma unroll
    for (int mi = 0; mi < 2; mi++) {
        int row0 = n0 + mw * 32 + mi * 16 + g;
#pragma unroll
        for (int j = 0; j < 8; j++) {
            int col = nw * 64 + 8 * j + 2 * tg;
            float b0 = root_b[col] + bias[col];
            float b1 = root_b[col + 1] + bias[col + 1];
            if (row0 < N_NODES)
                *(float2*)&out[(size_t)row0 * D + col] =
                    make_float2(acc[mi][j][0] + b0, acc[mi][j][1] + b1);
            if (row0 + 8 < N_NODES)
                *(float2*)&out[(size_t)(row0 + 8) * D + col] =
                    make_float2(acc[mi][j][2] + b0, acc[mi][j][3] + b1);
        }
    }
}

// ---------------------------------------------------------------------------
// Kernel: edge tiles — fp16 gather+GEMM, fp32 *ew + red.v4 scatter
// ---------------------------------------------------------------------------
extern "C" __global__ void __launch_bounds__(256, 2)
edge_kernel(const int* __restrict__ src, const int* __restrict__ dst,
            const float* __restrict__ ew, float* __restrict__ out) {
    extern __shared__ char smem[];
    const uint32_t sb = (uint32_t)__cvta_generic_to_shared(smem);
    const char* As = smem;
    const uint32_t* Bu = (const uint32_t*)(smem + A_BYTES);
    int* s_dst = (int*)(smem + SDST_BYTE);
    float* s_ew = (float*)(smem + SEW_BYTE);
    const uint32_t mbA = sb + MB_BYTE, mbB = mbA + 8;

    const int tid = threadIdx.x;
    const int r = blockIdx.y;
    const int ebase = r * N_EDGE + blockIdx.x * 128;

    if (tid == 0) { MBAR_INIT(mbA, 1); MBAR_INIT(mbB, 1); }
    __syncthreads();
    if (tid == 0) {
        MBAR_EXPECT(mbA, 128 * 256);
        MBAR_EXPECT(mbB, B_BYTES);
        bulk_cp(sb + A_BYTES, g_wth + (size_t)r * D * D, B_BYTES, mbB);
    }
    if (tid < 128) {
        int srow = __ldg(&src[ebase + tid]);
        bulk_cp(sb + tid * A_RB, g_xh + (size_t)srow * D, 256, mbA);
        s_dst[tid] = __ldg(&dst[ebase + tid]);
        s_ew[tid] = __ldg(&ew[ebase + tid]);
    }

    const int lane = tid & 31, warp = tid >> 5;
    const int g = lane >> 2, tg = lane & 3;
    const int mw = warp >> 1, nw = warp & 1;
    int boff[4];
    make_boff(lane, boff);

    float acc[2][8][4];
#pragma unroll
    for (int mi = 0; mi < 2; mi++)
#pragma unroll
        for (int j = 0; j < 8; j++)
#pragma unroll
            for (int c4 = 0; c4 < 4; c4++) acc[mi][j][c4] = 0.f;

    mbar_wait(mbA, 0);
    mbar_wait(mbB, 0);
    compute_tile(As, Bu, g, tg, mw, nw, boff, acc);

    __syncthreads();  // everyone done reading A/B (and s_dst/s_ew visible)

    // stage C*ew (fp32) over the A+B region for 128-bit coalesced REDs
    float* Cs = (float*)smem;
#pragma unroll
    for (int mi = 0; mi < 2; mi++) {
        int row0 = mw * 32 + mi * 16 + g;
        float w0 = s_ew[row0], w1 = s_ew[row0 + 8];
#pragma unroll
        for (int j = 0; j < 8; j++) {
            int col = nw * 64 + 8 * j + 2 * tg;
            *(float2*)&Cs[row0 * CS_STRIDE + col] =
                make_float2(acc[mi][j][0] * w0, acc[mi][j][1] * w0);
            *(float2*)&Cs[(row0 + 8) * CS_STRIDE + col] =
                make_float2(acc[mi][j][2] * w1, acc[mi][j][3] * w1);
        }
    }
    __syncthreads();

#pragma unroll
    for (int it = 0; it < 16; it++) {
        int t = tid + it * 256;
        int row = t >> 5, q = t & 31;
        const float4 v = *(const float4*)&Cs[row * CS_STRIDE + q * 4];
        float* p = out + (size_t)s_dst[row] * D + q * 4;
        asm volatile("red.global.add.v4.f32 [%0], {%1,%2,%3,%4};"
                     ::"l"(p), "f"(v.x), "f"(v.y), "f"(v.z), "f"(v.w)
                     : "memory");
    }
}

// ---------------------------------------------------------------------------
// ReLU
// ---------------------------------------------------------------------------
extern "C" __global__ void relu_kernel(float4* __restrict__ out, int n4) {
    int i = blockIdx.x * blockDim.x + threadIdx.x;
    int stride = gridDim.x * blockDim.x;
    for (; i < n4; i += stride) {
        float4 v = out[i];
        v.x = fmaxf(v.x, 0.f);
        v.y = fmaxf(v.y, 0.f);
        v.z = fmaxf(v.z, 0.f);
        v.w = fmaxf(v.w, 0.f);
        out[i] = v;
    }
}

extern "C" void kernel_launch(void* const* d_in, const int* in_sizes, int n_in,
                              void* d_out, int out_size) {
    const float* x      = (const float*)d_in[0];
    const int*   src    = (const int*)d_in[1];
    const int*   dst    = (const int*)d_in[2];
    const float* ew     = (const float*)d_in[3];
    const float* weight = (const float*)d_in[4];
    const float* root_w = (const float*)d_in[5];
    const float* root_b = (const float*)d_in[6];
    const float* bias   = (const float*)d_in[7];
    float* out = (float*)d_out;

    cudaFuncSetAttribute(root_kernel, cudaFuncAttributeMaxDynamicSharedMemorySize, ROOT_SMEM);
    cudaFuncSetAttribute(edge_kernel, cudaFuncAttributeMaxDynamicSharedMemorySize, EDGE_SMEM);

    int n8 = N_NODES * D / 8;
    xconv_kernel<<<(n8 + 255) / 256, 256>>>((const float4*)x);
    pack_w_kernel<<<N_REL + 1, 256>>>(weight, root_w);

    int root_blocks = (N_NODES + 127) / 128;  // 391
    root_kernel<<<root_blocks, 256, ROOT_SMEM>>>(root_b, bias, out);

    dim3 egrid(N_EDGE / 128, N_REL);  // 500 x 8
    edge_kernel<<<egrid, 256, EDGE_SMEM>>>(src, dst, ew, out);

    int n4 = out_size / 4;
    relu_kernel<<<1184, 256>>>((float4*)out, n4);
}

// round 14
// speedup vs baseline: 1.4064x; 1.0803x over previous
#include <cuda_runtime.h>
#include <cuda_fp16.h>
#include <cstdint>

#define N_NODES 50000
#define N_REL 8
#define N_EDGE 64000
#define D 128

#define A_RB 272                      // bytes per fp16 A row in smem (16B mult)
#define A_BYTES (128 * A_RB)          // 34816 per tile buffer
#define B_OFF (2 * A_BYTES)           // 69632
#define B_BYTES 32768                 // packed fp16 W image
#define MB_OFF (B_OFF + B_BYTES)      // 102400: mbA0|mbA1|mbB
#define SDST_OFF (MB_OFF + 32)        // 256 ints
#define SEW_OFF (SDST_OFF + 1024)     // 256 floats
#define EDGE_SMEM (SEW_OFF + 1024)    // 104480 B -> 2 CTAs/SM
#define CS_STRIDE 132                 // fp32 staging stride (64-row halves)

#define RMB_OFF (A_BYTES + B_BYTES)   // root: A(34816)+B(32768)
#define ROOT_SMEM (RMB_OFF + 16)

// fp16 images (static device scratch)
__device__ __align__(256) __half g_xh[N_NODES * D];
__device__ __align__(128) __half g_wth[N_REL * D * D];
__device__ __align__(128) __half g_rwh[D * D];

#define MBAR_INIT(mb, c) asm volatile("mbarrier.init.shared.b64 [%0], %1;" ::"r"(mb), "r"(c) : "memory")
#define MBAR_EXPECT(mb, bytes) asm volatile("mbarrier.arrive.expect_tx.shared.b64 _, [%0], %1;" ::"r"(mb), "r"(bytes) : "memory")

__device__ __forceinline__ void bulk_cp(uint32_t dst, const void* src, uint32_t bytes, uint32_t mb) {
    asm volatile(
        "cp.async.bulk.shared::cta.global.mbarrier::complete_tx::bytes [%0], [%1], %2, [%3];"
        ::"r"(dst), "l"(src), "r"(bytes), "r"(mb) : "memory");
}

// Bounded parity wait: protocol bug -> fast wrong answer, never a hung container.
__device__ __forceinline__ void mbar_wait(uint32_t mb, uint32_t parity) {
    for (int i = 0; i < (1 << 21); i++) {
        uint32_t done;
        asm volatile(
            "{\n\t.reg .pred p;\n\t"
            "mbarrier.try_wait.parity.acquire.cta.shared::cta.b64 p, [%1], %2;\n\t"
            "selp.b32 %0, 1, 0, p;\n\t}"
            : "=r"(done) : "r"(mb), "r"(parity) : "memory");
        if (done) return;
    }
}

__device__ __forceinline__ void mma_f16(float c[4], const uint32_t a[4],
                                        uint32_t b0, uint32_t b1) {
    asm volatile(
        "mma.sync.aligned.m16n8k16.row.col.f32.f16.f16.f32 "
        "{%0,%1,%2,%3}, {%4,%5,%6,%7}, {%8,%9}, {%0,%1,%2,%3};\n"
        : "+f"(c[0]), "+f"(c[1]), "+f"(c[2]), "+f"(c[3])
        : "r"(a[0]), "r"(a[1]), "r"(a[2]), "r"(a[3]), "r"(b0), "r"(b1));
}

// ---------------------------------------------------------------------------
// x -> fp16 conversion
// ---------------------------------------------------------------------------
__device__ __forceinline__ uint32_t f2h2(float a, float b) {
    __half2 h = __floats2half2_rn(a, b);
    return *(uint32_t*)&h;
}

extern "C" __global__ void xconv_kernel(const float4* __restrict__ x) {
    int i = blockIdx.x * blockDim.x + threadIdx.x;
    const int n8 = N_NODES * D / 8;
    if (i < n8) {
        float4 a = x[2 * i], b = x[2 * i + 1];
        uint4 u;
        u.x = f2h2(a.x, a.y);
        u.y = f2h2(a.z, a.w);
        u.z = f2h2(b.x, b.y);
        u.w = f2h2(b.z, b.w);
        *(uint4*)&g_xh[i * 8] = u;
    }
}

// ---------------------------------------------------------------------------
// W pack: fragment-order fp16 image (same as R13)
// ---------------------------------------------------------------------------
__device__ __forceinline__ int pack_half_idx(int k, int n) {
    int s = k >> 4, kl = k & 15, r = kl >> 3, tg = (kl >> 1) & 3, hi = kl & 1;
    int nw = n >> 6, j = (n & 63) >> 3, g = n & 7;
    int lane = g * 4 + tg, f = 2 * j + r;
    int u = lane * 4 + (f >> 2);
    int cp = (u & ~7) | ((u & 7) ^ ((u >> 3) & 7));
    return (s * 1024 + nw * 512 + cp * 4 + (f & 3)) * 2 + hi;
}

extern "C" __global__ void pack_w_kernel(const float* __restrict__ weight,
                                         const float* __restrict__ root_w) {
    int r = blockIdx.x;
    if (r < N_REL) {
        for (int i = threadIdx.x; i < D * D; i += blockDim.x) {
            int k = i >> 7, n = i & 127;
            g_wth[r * D * D + pack_half_idx(k, n)] = __float2half_rn(weight[r * D * D + i]);
        }
    } else {
        for (int i = threadIdx.x; i < D * D; i += blockDim.x) {
            int k = i >> 7, n = i & 127;
            g_rwh[pack_half_idx(k, n)] = __float2half_rn(root_w[i]);
        }
    }
}

__device__ __forceinline__ void make_boff(int lane, int boff[4]) {
    int lh = lane >> 1, sel = (lane & 1) * 4, x7 = lh & 7;
#pragma unroll
    for (int j = 0; j < 4; j++) boff[j] = (lh * 8 + ((sel + j) ^ x7)) * 4;
}

// full K=128 mainloop: 8 fp16 k16-steps
__device__ __forceinline__ void compute_tile(const char* __restrict__ As,
                                             const uint32_t* __restrict__ Bu,
                                             int g, int tg, int mw, int nw,
                                             const int boff[4],
                                             float acc[2][8][4]) {
#pragma unroll
    for (int s = 0; s < 8; s++) {
        uint32_t a[2][4];
#pragma unroll
        for (int mi = 0; mi < 2; mi++) {
            const char* Ar = As + (mw * 32 + mi * 16 + g) * A_RB + s * 32 + tg * 4;
            a[mi][0] = *(const uint32_t*)Ar;
            a[mi][1] = *(const uint32_t*)(Ar + 8 * A_RB);
            a[mi][2] = *(const uint32_t*)(Ar + 16);
            a[mi][3] = *(const uint32_t*)(Ar + 8 * A_RB + 16);
        }
        uint32_t bf[16];
        const uint32_t* Bk = Bu + s * 1024 + nw * 512;
#pragma unroll
        for (int j4 = 0; j4 < 4; j4++) {
            uint4 v = *(const uint4*)(Bk + boff[j4]);
            bf[4 * j4 + 0] = v.x;
            bf[4 * j4 + 1] = v.y;
            bf[4 * j4 + 2] = v.z;
            bf[4 * j4 + 3] = v.w;
        }
#pragma unroll
        for (int mi = 0; mi < 2; mi++)
#pragma unroll
            for (int j = 0; j < 8; j++)
                mma_f16(acc[mi][j], a[mi], bf[2 * j], bf[2 * j + 1]);
    }
}

// ---------------------------------------------------------------------------
// Kernel: root = x @ root_w + root_b + bias (dense init) — unchanged from R13
// ---------------------------------------------------------------------------
extern "C" __global__ void __launch_bounds__(256, 2)
root_kernel(const float* __restrict__ root_b, const float* __restrict__ bias,
            float* __restrict__ out) {
    extern __shared__ char smem[];
    const uint32_t sb = (uint32_t)__cvta_generic_to_shared(smem);
    const char* As = smem;
    const uint32_t* Bu = (const uint32_t*)(smem + A_BYTES);
    const uint32_t mbA = sb + RMB_OFF, mbB = mbA + 8;

    const int tid = threadIdx.x;
    const int n0 = blockIdx.x * 128;

    if (tid == 0) { MBAR_INIT(mbA, 1); MBAR_INIT(mbB, 1); }
    __syncthreads();
    if (tid == 0) {
        MBAR_EXPECT(mbA, 128 * 256);
        MBAR_EXPECT(mbB, B_BYTES);
        bulk_cp(sb + A_BYTES, g_rwh, B_BYTES, mbB);
    }
    if (tid < 128) {
        int gr = n0 + tid;
        if (gr >= N_NODES) gr = 0;
        bulk_cp(sb + tid * A_RB, g_xh + (size_t)gr * D, 256, mbA);
    }

    const int lane = tid & 31, warp = tid >> 5;
    const int g = lane >> 2, tg = lane & 3;
    const int mw = warp >> 1, nw = warp & 1;
    int boff[4];
    make_boff(lane, boff);

    float acc[2][8][4];
#pragma unroll
    for (int mi = 0; mi < 2; mi++)
#pragma unroll
        for (int j = 0; j < 8; j++)
#pragma unroll
            for (int c4 = 0; c4 < 4; c4++) acc[mi][j][c4] = 0.f;

    mbar_wait(mbA, 0);
    mbar_wait(mbB, 0);
    compute_tile(As, Bu, g, tg, mw, nw, boff, acc);

#pragma unroll
    for (int mi = 0; mi < 2; mi++) {
        int row0 = n0 + mw * 32 + mi * 16 + g;
#pragma unroll
        for (int j = 0; j < 8; j++) {
            int col = nw * 64 + 8 * j + 2 * tg;
            float b0 = root_b[col] + bias[col];
            float b1 = root_b[col + 1] + bias[col + 1];
            if (row0 < N_NODES)
                *(float2*)&out[(size_t)row0 * D + col] =
                    make_float2(acc[mi][j][0] + b0, acc[mi][j][1] + b1);
            if (row0 + 8 < N_NODES)
                *(float2*)&out[(size_t)(row0 + 8) * D + col] =
                    make_float2(acc[mi][j][2] + b0, acc[mi][j][3] + b1);
        }
    }
}

// ---------------------------------------------------------------------------
// Kernel: edge — 2 tiles per CTA, pipelined: both gathers + B issued upfront;
// scatter(t0) overlaps compute(t1). C staged in the dead A buffer in 64-row
// halves; fp32 red.v4 scatter.
// ---------------------------------------------------------------------------
extern "C" __global__ void __launch_bounds__(256, 2)
edge_kernel(const int* __restrict__ src, const int* __restrict__ dst,
            const float* __restrict__ ew, float* __restrict__ out) {
    extern __shared__ char smem[];
    const uint32_t sb = (uint32_t)__cvta_generic_to_shared(smem);
    const uint32_t mbA0 = sb + MB_OFF, mbA1 = mbA0 + 8, mbB = mbA0 + 16;
    int* s_dst = (int*)(smem + SDST_OFF);
    float* s_ew = (float*)(smem + SEW_OFF);

    const int tid = threadIdx.x;
    const int r = blockIdx.y;
    const int ebase = r * N_EDGE + blockIdx.x * 256;

    if (tid == 0) { MBAR_INIT(mbA0, 1); MBAR_INIT(mbA1, 1); MBAR_INIT(mbB, 1); }
    __syncthreads();
    if (tid == 0) {
        MBAR_EXPECT(mbA0, 128 * 256);
        MBAR_EXPECT(mbA1, 128 * 256);
        MBAR_EXPECT(mbB, B_BYTES);
        bulk_cp(sb + B_OFF, g_wth + (size_t)r * D * D, B_BYTES, mbB);
    }
    {
        int srow = __ldg(&src[ebase + tid]);
        int tt = tid >> 7, lrow = tid & 127;
        bulk_cp(sb + tt * A_BYTES + lrow * A_RB, g_xh + (size_t)srow * D, 256,
                tt ? mbA1 : mbA0);
        s_dst[tid] = __ldg(&dst[ebase + tid]);
        s_ew[tid] = __ldg(&ew[ebase + tid]);
    }

    const int lane = tid & 31, warp = tid >> 5;
    const int g = lane >> 2, tg = lane & 3;
    const int mw = warp >> 1, nw = warp & 1;
    int boff[4];
    make_boff(lane, boff);
    const uint32_t* Bu = (const uint32_t*)(smem + B_OFF);

#pragma unroll
    for (int t = 0; t < 2; t++) {
        float acc[2][8][4];
#pragma unroll
        for (int mi = 0; mi < 2; mi++)
#pragma unroll
            for (int j = 0; j < 8; j++)
#pragma unroll
                for (int c4 = 0; c4 < 4; c4++) acc[mi][j][c4] = 0.f;

        mbar_wait(t ? mbA1 : mbA0, 0);
        if (t == 0) mbar_wait(mbB, 0);
        compute_tile(smem + t * A_BYTES, Bu, g, tg, mw, nw, boff, acc);

        float* Cs = (float*)(smem + t * A_BYTES);  // dead A buffer of this tile
#pragma unroll
        for (int h = 0; h < 2; h++) {
            __syncthreads();  // h0: compute done (A dead); h1: scatter-h0 reads done
            if ((mw >> 1) == h) {
                const int mwl = mw & 1;
#pragma unroll
                for (int mi = 0; mi < 2; mi++) {
                    int lrow = mwl * 32 + mi * 16 + g;      // 0..63
                    int erow = t * 128 + h * 64 + lrow;
                    float w0 = s_ew[erow], w1 = s_ew[erow + 8];
#pragma unroll
                    for (int j = 0; j < 8; j++) {
                        int col = nw * 64 + 8 * j + 2 * tg;
                        *(float2*)&Cs[lrow * CS_STRIDE + col] =
                            make_float2(acc[mi][j][0] * w0, acc[mi][j][1] * w0);
                        *(float2*)&Cs[(lrow + 8) * CS_STRIDE + col] =
                            make_float2(acc[mi][j][2] * w1, acc[mi][j][3] * w1);
                    }
                }
            }
            __syncthreads();  // staging visible
#pragma unroll
            for (int it = 0; it < 8; it++) {
                int s2 = tid + it * 256;
                int lrow = s2 >> 5, q = s2 & 31;
                int d = s_dst[t * 128 + h * 64 + lrow];
                const float4 v = *(const float4*)&Cs[lrow * CS_STRIDE + q * 4];
                float* p = out + (size_t)d * D + q * 4;
                asm volatile("red.global.add.v4.f32 [%0], {%1,%2,%3,%4};"
                             ::"l"(p), "f"(v.x), "f"(v.y), "f"(v.z), "f"(v.w)
                             : "memory");
            }
        }
        // no sync: scatter(t) drains while compute(t+1) runs (disjoint smem)
    }
}

// ---------------------------------------------------------------------------
// ReLU
// ---------------------------------------------------------------------------
extern "C" __global__ void relu_kernel(float4* __restrict__ out, int n4) {
    int i = blockIdx.x * blockDim.x + threadIdx.x;
    int stride = gridDim.x * blockDim.x;
    for (; i < n4; i += stride) {
        float4 v = out[i];
        v.x = fmaxf(v.x, 0.f);
        v.y = fmaxf(v.y, 0.f);
        v.z = fmaxf(v.z, 0.f);
        v.w = fmaxf(v.w, 0.f);
        out[i] = v;
    }
}

extern "C" void kernel_launch(void* const* d_in, const int* in_sizes, int n_in,
                              void* d_out, int out_size) {
    const float* x      = (const float*)d_in[0];
    const int*   src    = (const int*)d_in[1];
    const int*   dst    = (const int*)d_in[2];
    const float* ew     = (const float*)d_in[3];
    const float* weight = (const float*)d_in[4];
    const float* root_w = (const float*)d_in[5];
    const float* root_b = (const float*)d_in[6];
    const float* bias   = (const float*)d_in[7];
    float* out = (float*)d_out;

    cudaFuncSetAttribute(root_kernel, cudaFuncAttributeMaxDynamicSharedMemorySize, ROOT_SMEM);
    cudaFuncSetAttribute(edge_kernel, cudaFuncAttributeMaxDynamicSharedMemorySize, EDGE_SMEM);

    int n8 = N_NODES * D / 8;
    xconv_kernel<<<(n8 + 255) / 256, 256>>>((const float4*)x);
    pack_w_kernel<<<N_REL + 1, 256>>>(weight, root_w);

    int root_blocks = (N_NODES + 127) / 128;  // 391
    root_kernel<<<root_blocks, 256, ROOT_SMEM>>>(root_b, bias, out);

    dim3 egrid(N_EDGE / 256, N_REL);  // 250 x 8 = 2000 CTAs
    edge_kernel<<<egrid, 256, EDGE_SMEM>>>(src, dst, ew, out);

    int n4 = out_size / 4;
    relu_kernel<<<1184, 256>>>((float4*)out, n4);
}